// round 2
// baseline (speedup 1.0000x reference)
#include <cuda_runtime.h>
#include <math.h>

// Problem shape constants
#define BB 8
#define LL 512
#define NN 2048
#define CC 1024
#define DD 128

// Scratch (device globals — no allocations allowed)
__device__ float g_q[BB * NN * DD];          // 8 MiB
__device__ float g_k[BB * NN * DD];          // 8 MiB
__device__ float g_attn[(long long)BB * NN * NN];  // 128 MiB

// ---------------------------------------------------------------------------
// Generic NT GEMM: C[m,n] = sum_k A[m,k] * B[n,k]  (+ bias[n])
// A row-major [M,K], B row-major [N,K], C row-major [M,N]
// blockIdx.z selects batch via strides. Requires M%64==0, N%64==0, K%16==0.
// ---------------------------------------------------------------------------
#define TBM 64
#define TBN 64
#define TBK 16

__global__ __launch_bounds__(256) void gemm_nt_kernel(
    const float* __restrict__ A, const float* __restrict__ B,
    float* __restrict__ C, const float* __restrict__ bias,
    int M, int N, int K,
    long long sA, long long sB, long long sC)
{
    __shared__ float As[TBK][TBM + 4];
    __shared__ float Bs[TBK][TBN + 4];

    const int bz = blockIdx.z;
    A += (long long)bz * sA;
    B += (long long)bz * sB;
    C += (long long)bz * sC;

    const int tid = threadIdx.x;          // 0..255
    const int row0 = blockIdx.y * TBM;
    const int col0 = blockIdx.x * TBN;

    const int tx = tid & 15;              // 0..15 -> N dir
    const int ty = tid >> 4;              // 0..15 -> M dir

    // Loader mapping: 256 threads x 1 float4 = 64 rows x 16 k
    const int lrow = tid >> 2;            // 0..63
    const int lk4  = (tid & 3) << 2;      // 0,4,8,12

    float acc[4][4];
    #pragma unroll
    for (int i = 0; i < 4; i++)
        #pragma unroll
        for (int j = 0; j < 4; j++) acc[i][j] = 0.0f;

    for (int k0 = 0; k0 < K; k0 += TBK) {
        float4 av = *reinterpret_cast<const float4*>(
            &A[(long long)(row0 + lrow) * K + k0 + lk4]);
        float4 bv = *reinterpret_cast<const float4*>(
            &B[(long long)(col0 + lrow) * K + k0 + lk4]);
        As[lk4 + 0][lrow] = av.x; As[lk4 + 1][lrow] = av.y;
        As[lk4 + 2][lrow] = av.z; As[lk4 + 3][lrow] = av.w;
        Bs[lk4 + 0][lrow] = bv.x; Bs[lk4 + 1][lrow] = bv.y;
        Bs[lk4 + 2][lrow] = bv.z; Bs[lk4 + 3][lrow] = bv.w;
        __syncthreads();

        #pragma unroll
        for (int k = 0; k < TBK; k++) {
            float ar[4], br[4];
            #pragma unroll
            for (int i = 0; i < 4; i++) ar[i] = As[k][ty * 4 + i];
            #pragma unroll
            for (int j = 0; j < 4; j++) br[j] = Bs[k][tx * 4 + j];
            #pragma unroll
            for (int i = 0; i < 4; i++)
                #pragma unroll
                for (int j = 0; j < 4; j++)
                    acc[i][j] = fmaf(ar[i], br[j], acc[i][j]);
        }
        __syncthreads();
    }

    #pragma unroll
    for (int i = 0; i < 4; i++) {
        const int r = row0 + ty * 4 + i;
        #pragma unroll
        for (int j = 0; j < 4; j++) {
            const int c = col0 + tx * 4 + j;
            float v = acc[i][j];
            if (bias) v += bias[c];
            C[(long long)r * N + c] = v;
        }
    }
}

// ---------------------------------------------------------------------------
// Row softmax in-place. One block (256 threads) per row of length n.
// ---------------------------------------------------------------------------
__global__ __launch_bounds__(256) void softmax_rows_kernel(float* __restrict__ data, int n)
{
    float* row = data + (long long)blockIdx.x * n;
    const int tid = threadIdx.x;
    __shared__ float red[32];

    // max
    float lmax = -INFINITY;
    for (int i = tid; i < n; i += 256) lmax = fmaxf(lmax, row[i]);
    #pragma unroll
    for (int o = 16; o; o >>= 1) lmax = fmaxf(lmax, __shfl_xor_sync(0xffffffffu, lmax, o));
    if ((tid & 31) == 0) red[tid >> 5] = lmax;
    __syncthreads();
    if (tid < 32) {
        float v = (tid < 8) ? red[tid] : -INFINITY;
        #pragma unroll
        for (int o = 4; o; o >>= 1) v = fmaxf(v, __shfl_xor_sync(0xffffffffu, v, o));
        if (tid == 0) red[0] = v;
    }
    __syncthreads();
    const float m = red[0];
    __syncthreads();

    // exp + sum
    float lsum = 0.0f;
    for (int i = tid; i < n; i += 256) {
        float e = __expf(row[i] - m);
        row[i] = e;
        lsum += e;
    }
    #pragma unroll
    for (int o = 16; o; o >>= 1) lsum += __shfl_xor_sync(0xffffffffu, lsum, o);
    if ((tid & 31) == 0) red[tid >> 5] = lsum;
    __syncthreads();
    if (tid < 32) {
        float v = (tid < 8) ? red[tid] : 0.0f;
        #pragma unroll
        for (int o = 4; o; o >>= 1) v += __shfl_xor_sync(0xffffffffu, v, o);
        if (tid == 0) red[0] = v;
    }
    __syncthreads();
    const float inv = 1.0f / red[0];

    for (int i = tid; i < n; i += 256) row[i] *= inv;
}

// ---------------------------------------------------------------------------
// Launch
// ---------------------------------------------------------------------------
extern "C" void kernel_launch(void* const* d_in, const int* in_sizes, int n_in,
                              void* d_out, int out_size)
{
    const float* logits   = (const float*)d_in[0];  // [B,L,N]
    const float* features = (const float*)d_in[1];  // [B,N,C]
    const float* Wq       = (const float*)d_in[2];  // [D,C]
    const float* bq       = (const float*)d_in[3];  // [D]
    const float* Wk       = (const float*)d_in[4];  // [D,C]
    const float* bk       = (const float*)d_in[5];  // [D]
    float* out            = (float*)d_out;          // [B,L,N]

    float *q_ptr, *k_ptr, *attn_ptr;
    cudaGetSymbolAddress((void**)&q_ptr, g_q);
    cudaGetSymbolAddress((void**)&k_ptr, g_k);
    cudaGetSymbolAddress((void**)&attn_ptr, g_attn);

    // 1+2) Projections: [B*N, C] x [D, C]^T -> [B*N, D]
    {
        dim3 grid(DD / TBN, (BB * NN) / TBM, 1);
        gemm_nt_kernel<<<grid, 256>>>(features, Wq, q_ptr, bq,
                                      BB * NN, DD, CC, 0, 0, 0);
        gemm_nt_kernel<<<grid, 256>>>(features, Wk, k_ptr, bk,
                                      BB * NN, DD, CC, 0, 0, 0);
    }

    // 3) Energy: per batch Q[2048,128] @ K^T -> [2048,2048]
    {
        dim3 grid(NN / TBN, NN / TBM, BB);
        gemm_nt_kernel<<<grid, 256>>>(q_ptr, k_ptr, attn_ptr, nullptr,
                                      NN, NN, DD,
                                      (long long)NN * DD, (long long)NN * DD,
                                      (long long)NN * NN);
    }

    // 4) Softmax over last dim, in place
    softmax_rows_kernel<<<BB * NN, 256>>>(attn_ptr, NN);

    // 5) x_m[b,l,m] = sum_n logits[b,l,n] * attn[b,m,n]  (NT GEMM)
    {
        dim3 grid(NN / TBN, LL / TBM, BB);
        gemm_nt_kernel<<<grid, 256>>>(logits, attn_ptr, out, nullptr,
                                      LL, NN, NN,
                                      (long long)LL * NN, (long long)NN * NN,
                                      (long long)LL * NN);
    }
}

// round 4
// speedup vs baseline: 1.0939x; 1.0939x over previous
#include <cuda_runtime.h>
#include <cuda_bf16.h>
#include <math.h>
#include <stdint.h>

// Problem shape constants
#define BB 8
#define LL 512
#define NN 2048
#define CC 1024
#define DD 128

// Scratch (device globals — no allocations allowed)
__device__ float g_q[BB * NN * DD];                 // 8 MiB
__device__ float g_k[BB * NN * DD];                 // 8 MiB
__device__ float g_attn[(long long)BB * NN * NN];   // 128 MiB

// ===========================================================================
// Family-portable tensor-core primitives (NO tcgen05 — ptxas targets sm_103)
// ===========================================================================
__device__ __forceinline__ uint32_t smem_u32(const void* p) {
    uint32_t a;
    asm("{ .reg .u64 t; cvta.to.shared.u64 t, %1; cvt.u32.u64 %0, t; }"
        : "=r"(a) : "l"(p));
    return a;
}

__device__ __forceinline__ uint32_t sw128(uint32_t off) {
    return off ^ ((off >> 3) & 0x70);
}

__device__ __forceinline__ void ldm_x4(uint32_t r[4], uint32_t addr) {
    asm volatile("ldmatrix.sync.aligned.m8n8.x4.shared.b16 {%0,%1,%2,%3}, [%4];"
                 : "=r"(r[0]), "=r"(r[1]), "=r"(r[2]), "=r"(r[3])
                 : "r"(addr));
}

__device__ __forceinline__ void mma_bf16(float d[4], const uint32_t a[4],
                                         uint32_t b0, uint32_t b1) {
    asm volatile(
        "mma.sync.aligned.m16n8k16.row.col.f32.bf16.bf16.f32 "
        "{%0,%1,%2,%3}, {%4,%5,%6,%7}, {%8,%9}, {%0,%1,%2,%3};"
        : "+f"(d[0]), "+f"(d[1]), "+f"(d[2]), "+f"(d[3])
        : "r"(a[0]), "r"(a[1]), "r"(a[2]), "r"(a[3]), "r"(b0), "r"(b1));
}

// split fp32 -> (bf16 hi, bf16 lo) packed pairs
__device__ __forceinline__ void split2(float x0, float x1, uint32_t& hi, uint32_t& lo) {
    __nv_bfloat16 h0 = __float2bfloat16_rn(x0);
    __nv_bfloat16 h1 = __float2bfloat16_rn(x1);
    __nv_bfloat16 l0 = __float2bfloat16_rn(x0 - __bfloat162float(h0));
    __nv_bfloat16 l1 = __float2bfloat16_rn(x1 - __bfloat162float(h1));
    hi = ((uint32_t)__bfloat16_as_ushort(h1) << 16) | __bfloat16_as_ushort(h0);
    lo = ((uint32_t)__bfloat16_as_ushort(l1) << 16) | __bfloat16_as_ushort(l0);
}

// convert 32 floats (8 float4) of one smem row-half into hi/lo bf16 tiles
__device__ __forceinline__ void conv_store(const float4* v, char* hi, char* lo,
                                           int row, int half) {
    #pragma unroll
    for (int j = 0; j < 8; j += 2) {
        uint32_t h[4], l[4];
        split2(v[j].x,     v[j].y,     h[0], l[0]);
        split2(v[j].z,     v[j].w,     h[1], l[1]);
        split2(v[j + 1].x, v[j + 1].y, h[2], l[2]);
        split2(v[j + 1].z, v[j + 1].w, h[3], l[3]);
        uint32_t off = sw128((uint32_t)(row * 128 + (half + j * 4) * 2));
        *reinterpret_cast<uint4*>(hi + off) = make_uint4(h[0], h[1], h[2], h[3]);
        *reinterpret_cast<uint4*>(lo + off) = make_uint4(l[0], l[1], l[2], l[3]);
    }
}

// ===========================================================================
// Generic HMMA NT GEMM: C[m,n] = sum_k A[m,k]*B[n,k] (+ bias[n])
// CTA tile 128x128, K-chunk 64, 2-stage double buffer, 3-term bf16 split.
// Requires M%128==0, N%128==0, K%64==0. 256 threads (8 warps: 4m x 2n).
// ===========================================================================
#define STAGE_BYTES 65536
#define HM_SMEM (2 * STAGE_BYTES)

__global__ __launch_bounds__(256, 1) void hmma_nt_kernel(
    const float* __restrict__ A, const float* __restrict__ B,
    float* __restrict__ C, const float* __restrict__ bias,
    int M, int N, int K,
    long long sA, long long sB, long long sC)
{
    extern __shared__ char smem[];
    const uint32_t sbase = smem_u32(smem);
    const int tid  = threadIdx.x;
    const int lane = tid & 31;
    const int wid  = tid >> 5;

    const int bz = blockIdx.z;
    const int m0 = blockIdx.y * 128;
    const int n0 = blockIdx.x * 128;

    const float* Ag = A + bz * sA + (long long)m0 * K;
    const float* Bg = B + bz * sB + (long long)n0 * K;
    float*       Cg = C + bz * sC;

    // loader mapping: thread -> (row, 32-elem half) of the 128x64 fp32 tile
    const int lrow  = tid >> 1;
    const int lhalf = (tid & 1) * 32;
    const float* aG = Ag + (long long)lrow * K + lhalf;
    const float* bG = Bg + (long long)lrow * K + lhalf;

    // warp tiling: warp tile 32(m) x 64(n)
    const int wm = (wid & 3) * 32;
    const int wn = (wid >> 2) * 64;
    const int qq = lane >> 3;
    const int rr = lane & 7;

    float acc[2][8][4];
    #pragma unroll
    for (int mi = 0; mi < 2; mi++)
        #pragma unroll
        for (int ni = 0; ni < 8; ni++)
            #pragma unroll
            for (int c = 0; c < 4; c++) acc[mi][ni][c] = 0.0f;

    const int nch = K / 64;

    float4 av[8], bv[8];
    #pragma unroll
    for (int j = 0; j < 8; ++j) {
        av[j] = *reinterpret_cast<const float4*>(aG + j * 4);
        bv[j] = *reinterpret_cast<const float4*>(bG + j * 4);
    }
    conv_store(av, smem,         smem + 16384, lrow, lhalf);
    conv_store(bv, smem + 32768, smem + 49152, lrow, lhalf);
    __syncthreads();

    for (int it = 0; it < nch; ++it) {
        const int cur = it & 1;
        const uint32_t st = sbase + cur * STAGE_BYTES;

        // prefetch next chunk into registers (hidden under the MMA loop)
        if (it + 1 < nch) {
            const float* aN = aG + (it + 1) * 64;
            const float* bN = bG + (it + 1) * 64;
            #pragma unroll
            for (int j = 0; j < 8; ++j) {
                av[j] = *reinterpret_cast<const float4*>(aN + j * 4);
                bv[j] = *reinterpret_cast<const float4*>(bN + j * 4);
            }
        }

        // MMA over the current stage: 4 k-steps of 16
        #pragma unroll
        for (int ks = 0; ks < 4; ++ks) {
            const int ko = ks * 16;
            uint32_t ah[2][4], al[2][4], bb[4][4];
            uint32_t aoff[2], boff[4];
            #pragma unroll
            for (int mi = 0; mi < 2; ++mi) {
                aoff[mi] = sw128((uint32_t)((wm + mi * 16 + rr + (qq & 1) * 8) * 128
                                            + (ko + (qq >> 1) * 8) * 2));
                ldm_x4(ah[mi], st + aoff[mi]);
                ldm_x4(al[mi], st + 16384 + aoff[mi]);
            }
            #pragma unroll
            for (int bi = 0; bi < 4; ++bi) {
                boff[bi] = sw128((uint32_t)((wn + bi * 16 + rr + (qq >> 1) * 8) * 128
                                            + (ko + (qq & 1) * 8) * 2));
                ldm_x4(bb[bi], st + 32768 + boff[bi]);
            }
            // hi*hi
            #pragma unroll
            for (int mi = 0; mi < 2; ++mi)
                #pragma unroll
                for (int ni = 0; ni < 8; ++ni)
                    mma_bf16(acc[mi][ni], ah[mi],
                             bb[ni >> 1][(ni & 1) * 2], bb[ni >> 1][(ni & 1) * 2 + 1]);
            // lo*hi
            #pragma unroll
            for (int mi = 0; mi < 2; ++mi)
                #pragma unroll
                for (int ni = 0; ni < 8; ++ni)
                    mma_bf16(acc[mi][ni], al[mi],
                             bb[ni >> 1][(ni & 1) * 2], bb[ni >> 1][(ni & 1) * 2 + 1]);
            // hi*lo (reuse bb regs for B_lo)
            #pragma unroll
            for (int bi = 0; bi < 4; ++bi)
                ldm_x4(bb[bi], st + 49152 + boff[bi]);
            #pragma unroll
            for (int mi = 0; mi < 2; ++mi)
                #pragma unroll
                for (int ni = 0; ni < 8; ++ni)
                    mma_bf16(acc[mi][ni], ah[mi],
                             bb[ni >> 1][(ni & 1) * 2], bb[ni >> 1][(ni & 1) * 2 + 1]);
        }

        if (it + 1 < nch) {
            char* st2 = smem + ((it + 1) & 1) * STAGE_BYTES;
            conv_store(av, st2,         st2 + 16384, lrow, lhalf);
            conv_store(bv, st2 + 32768, st2 + 49152, lrow, lhalf);
            __syncthreads();
        }
    }

    // epilogue: write accumulators (+ optional bias)
    const int g  = lane >> 2;
    const int t4 = lane & 3;
    #pragma unroll
    for (int mi = 0; mi < 2; ++mi) {
        const int row = m0 + wm + mi * 16 + g;
        #pragma unroll
        for (int ni = 0; ni < 8; ++ni) {
            const int col = n0 + wn + ni * 8 + t4 * 2;
            float b0 = 0.0f, b1 = 0.0f;
            if (bias) { b0 = bias[col]; b1 = bias[col + 1]; }
            float2 v0 = make_float2(acc[mi][ni][0] + b0, acc[mi][ni][1] + b1);
            float2 v1 = make_float2(acc[mi][ni][2] + b0, acc[mi][ni][3] + b1);
            *reinterpret_cast<float2*>(&Cg[(long long)row * N + col])       = v0;
            *reinterpret_cast<float2*>(&Cg[(long long)(row + 8) * N + col]) = v1;
        }
    }
}

// ---------------------------------------------------------------------------
// Row softmax in-place. One block (256 threads) per row of length n.
// ---------------------------------------------------------------------------
__global__ __launch_bounds__(256) void softmax_rows_kernel(float* __restrict__ data, int n)
{
    float* row = data + (long long)blockIdx.x * n;
    const int tid = threadIdx.x;
    __shared__ float red[32];

    float lmax = -INFINITY;
    for (int i = tid; i < n; i += 256) lmax = fmaxf(lmax, row[i]);
    #pragma unroll
    for (int o = 16; o; o >>= 1) lmax = fmaxf(lmax, __shfl_xor_sync(0xffffffffu, lmax, o));
    if ((tid & 31) == 0) red[tid >> 5] = lmax;
    __syncthreads();
    if (tid < 32) {
        float v = (tid < 8) ? red[tid] : -INFINITY;
        #pragma unroll
        for (int o = 4; o; o >>= 1) v = fmaxf(v, __shfl_xor_sync(0xffffffffu, v, o));
        if (tid == 0) red[0] = v;
    }
    __syncthreads();
    const float m = red[0];
    __syncthreads();

    float lsum = 0.0f;
    for (int i = tid; i < n; i += 256) {
        float e = __expf(row[i] - m);
        row[i] = e;
        lsum += e;
    }
    #pragma unroll
    for (int o = 16; o; o >>= 1) lsum += __shfl_xor_sync(0xffffffffu, lsum, o);
    if ((tid & 31) == 0) red[tid >> 5] = lsum;
    __syncthreads();
    if (tid < 32) {
        float v = (tid < 8) ? red[tid] : 0.0f;
        #pragma unroll
        for (int o = 4; o; o >>= 1) v += __shfl_xor_sync(0xffffffffu, v, o);
        if (tid == 0) red[0] = v;
    }
    __syncthreads();
    const float inv = 1.0f / red[0];

    for (int i = tid; i < n; i += 256) row[i] *= inv;
}

// ---------------------------------------------------------------------------
// Launch
// ---------------------------------------------------------------------------
extern "C" void kernel_launch(void* const* d_in, const int* in_sizes, int n_in,
                              void* d_out, int out_size)
{
    const float* logits   = (const float*)d_in[0];  // [B,L,N]
    const float* features = (const float*)d_in[1];  // [B,N,C]
    const float* Wq       = (const float*)d_in[2];  // [D,C]
    const float* bq       = (const float*)d_in[3];  // [D]
    const float* Wk       = (const float*)d_in[4];  // [D,C]
    const float* bk       = (const float*)d_in[5];  // [D]
    float* out            = (float*)d_out;          // [B,L,N]

    float *q_ptr, *k_ptr, *attn_ptr;
    cudaGetSymbolAddress((void**)&q_ptr, g_q);
    cudaGetSymbolAddress((void**)&k_ptr, g_k);
    cudaGetSymbolAddress((void**)&attn_ptr, g_attn);

    cudaFuncSetAttribute(hmma_nt_kernel,
                         cudaFuncAttributeMaxDynamicSharedMemorySize, HM_SMEM);

    // 1+2) Projections: [B*N=16384, C=1024] x [D=128, C]^T -> [B*N, D]
    hmma_nt_kernel<<<dim3(1, (BB * NN) / 128, 1), 256, HM_SMEM>>>(
        features, Wq, q_ptr, bq, BB * NN, DD, CC, 0, 0, 0);
    hmma_nt_kernel<<<dim3(1, (BB * NN) / 128, 1), 256, HM_SMEM>>>(
        features, Wk, k_ptr, bk, BB * NN, DD, CC, 0, 0, 0);

    // 3) Energy: per batch Q[2048,128] @ K^T -> [2048,2048]
    hmma_nt_kernel<<<dim3(NN / 128, NN / 128, BB), 256, HM_SMEM>>>(
        q_ptr, k_ptr, attn_ptr, nullptr, NN, NN, DD,
        (long long)NN * DD, (long long)NN * DD, (long long)NN * NN);

    // 4) Softmax over last dim, in place
    softmax_rows_kernel<<<BB * NN, 256>>>(attn_ptr, NN);

    // 5) Aggregation: out[b,l,m] = sum_n logits[b,l,n]*attn[b,m,n]
    hmma_nt_kernel<<<dim3(NN / 128, LL / 128, BB), 256, HM_SMEM>>>(
        logits, attn_ptr, out, nullptr, LL, NN, NN,
        (long long)LL * NN, (long long)NN * NN, (long long)LL * NN);
}

// round 5
// speedup vs baseline: 3.2859x; 3.0039x over previous
#include <cuda_runtime.h>
#include <cuda_bf16.h>
#include <math.h>
#include <stdint.h>

// Problem shape constants
#define BB 8
#define LL 512
#define NN 2048
#define CC 1024
#define DD 128

// ---------------------------------------------------------------------------
// Scratch (device globals — no allocations allowed)
// ---------------------------------------------------------------------------
__device__ __align__(16) __nv_bfloat16 g_feat_h[BB * NN * CC];   // 32 MB
__device__ __align__(16) __nv_bfloat16 g_feat_l[BB * NN * CC];
__device__ __align__(16) __nv_bfloat16 g_log_h[BB * LL * NN];    // 16 MB
__device__ __align__(16) __nv_bfloat16 g_log_l[BB * LL * NN];
__device__ __align__(16) __nv_bfloat16 g_wq_h[DD * CC];
__device__ __align__(16) __nv_bfloat16 g_wq_l[DD * CC];
__device__ __align__(16) __nv_bfloat16 g_wk_h[DD * CC];
__device__ __align__(16) __nv_bfloat16 g_wk_l[DD * CC];
__device__ __align__(16) __nv_bfloat16 g_q_h[BB * NN * DD];      // 4 MB
__device__ __align__(16) __nv_bfloat16 g_q_l[BB * NN * DD];
__device__ __align__(16) __nv_bfloat16 g_k_h[BB * NN * DD];
__device__ __align__(16) __nv_bfloat16 g_k_l[BB * NN * DD];
__device__ __align__(16) float g_energy[(size_t)BB * NN * NN];   // 128 MB
__device__ __align__(16) __nv_bfloat16 g_attn_h[(size_t)BB * NN * NN]; // 64 MB
__device__ __align__(16) __nv_bfloat16 g_attn_l[(size_t)BB * NN * NN]; // 64 MB

// ---------------------------------------------------------------------------
// Helpers (family-portable PTX only: ldmatrix / mma.sync / cp.async)
// ---------------------------------------------------------------------------
__device__ __forceinline__ uint32_t smem_u32(const void* p) {
    uint32_t a;
    asm("{ .reg .u64 t; cvta.to.shared.u64 t, %1; cvt.u32.u64 %0, t; }"
        : "=r"(a) : "l"(p));
    return a;
}

__device__ __forceinline__ uint32_t sw128(uint32_t off) {
    return off ^ ((off >> 3) & 0x70);
}

__device__ __forceinline__ void ldm_x4(uint32_t r[4], uint32_t addr) {
    asm volatile("ldmatrix.sync.aligned.m8n8.x4.shared.b16 {%0,%1,%2,%3}, [%4];"
                 : "=r"(r[0]), "=r"(r[1]), "=r"(r[2]), "=r"(r[3])
                 : "r"(addr));
}

__device__ __forceinline__ void mma_bf16(float d[4], const uint32_t a[4],
                                         uint32_t b0, uint32_t b1) {
    asm volatile(
        "mma.sync.aligned.m16n8k16.row.col.f32.bf16.bf16.f32 "
        "{%0,%1,%2,%3}, {%4,%5,%6,%7}, {%8,%9}, {%0,%1,%2,%3};"
        : "+f"(d[0]), "+f"(d[1]), "+f"(d[2]), "+f"(d[3])
        : "r"(a[0]), "r"(a[1]), "r"(a[2]), "r"(a[3]), "r"(b0), "r"(b1));
}

__device__ __forceinline__ void cpa16(uint32_t dst, const void* src) {
    asm volatile("cp.async.cg.shared.global [%0], [%1], 16;"
                 :: "r"(dst), "l"(src));
}
__device__ __forceinline__ void cp_commit() {
    asm volatile("cp.async.commit_group;" ::: "memory");
}
__device__ __forceinline__ void cp_wait1() {
    asm volatile("cp.async.wait_group 1;" ::: "memory");
}
__device__ __forceinline__ void cp_wait0() {
    asm volatile("cp.async.wait_group 0;" ::: "memory");
}

// split fp32 -> (bf16 hi, bf16 lo) packed pairs
__device__ __forceinline__ void split2(float x0, float x1, uint32_t& hi, uint32_t& lo) {
    __nv_bfloat16 h0 = __float2bfloat16_rn(x0);
    __nv_bfloat16 h1 = __float2bfloat16_rn(x1);
    __nv_bfloat16 l0 = __float2bfloat16_rn(x0 - __bfloat162float(h0));
    __nv_bfloat16 l1 = __float2bfloat16_rn(x1 - __bfloat162float(h1));
    hi = ((uint32_t)__bfloat16_as_ushort(h1) << 16) | __bfloat16_as_ushort(h0);
    lo = ((uint32_t)__bfloat16_as_ushort(l1) << 16) | __bfloat16_as_ushort(l0);
}

// ---------------------------------------------------------------------------
// Elementwise split: fp32 -> hi/lo bf16 (4 elements / thread)
// ---------------------------------------------------------------------------
__global__ __launch_bounds__(256) void split_kernel(
    const float4* __restrict__ src, uint2* __restrict__ hi,
    uint2* __restrict__ lo, int n4)
{
    int i = blockIdx.x * 256 + threadIdx.x;
    if (i < n4) {
        float4 v = src[i];
        uint32_t h0, l0, h1, l1;
        split2(v.x, v.y, h0, l0);
        split2(v.z, v.w, h1, l1);
        hi[i] = make_uint2(h0, h1);
        lo[i] = make_uint2(l0, l1);
    }
}

// ---------------------------------------------------------------------------
// bf16 HMMA NT GEMM with 3-term split: C = Ah*Bh + Al*Bh + Ah*Bl
// A tiles [M,K] bf16 row-major (hi+lo), B tiles [N,K] bf16 row-major (hi+lo).
// CTA tile 128x128, K-chunk 64, 3-stage cp.async pipeline.
// Output: fp32 (Cf) and/or bf16 hi/lo (Ch/Cl), + optional bias.
// ---------------------------------------------------------------------------
#define NSTAGE 3
#define STAGE_BYTES 65536   // Ah 16K | Al 16K | Bh 16K | Bl 16K
#define GSMEM (NSTAGE * STAGE_BYTES)

__device__ __forceinline__ void fill_stage(uint32_t st,
    const __nv_bfloat16* __restrict__ ah, const __nv_bfloat16* __restrict__ al,
    const __nv_bfloat16* __restrict__ bh, const __nv_bfloat16* __restrict__ bl,
    int K, int tid)
{
    #pragma unroll
    for (int i = 0; i < 4; ++i) {
        const int id  = tid + (i << 8);
        const int row = id >> 3, g = id & 7;
        const long long goff = (long long)row * K + (g << 3);
        const uint32_t so = sw128((uint32_t)((row << 7) + (g << 4)));
        cpa16(st + so,          ah + goff);
        cpa16(st + 16384 + so,  al + goff);
        cpa16(st + 32768 + so,  bh + goff);
        cpa16(st + 49152 + so,  bl + goff);
    }
    cp_commit();
}

__global__ __launch_bounds__(256, 1) void hgemm_nt(
    const __nv_bfloat16* __restrict__ Ah, const __nv_bfloat16* __restrict__ Al,
    const __nv_bfloat16* __restrict__ Bh, const __nv_bfloat16* __restrict__ Bl,
    float* __restrict__ Cf,
    __nv_bfloat16* __restrict__ Ch, __nv_bfloat16* __restrict__ Cl,
    const float* __restrict__ bias,
    int M, int N, int K,
    long long sA, long long sB, long long sC)
{
    extern __shared__ char smem[];
    const uint32_t sbase = smem_u32(smem);
    const int tid  = threadIdx.x;
    const int lane = tid & 31;
    const int wid  = tid >> 5;

    const int bz = blockIdx.z;
    const int m0 = blockIdx.y * 128;
    const int n0 = blockIdx.x * 128;

    const __nv_bfloat16* Aht = Ah + bz * sA + (long long)m0 * K;
    const __nv_bfloat16* Alt = Al + bz * sA + (long long)m0 * K;
    const __nv_bfloat16* Bht = Bh + bz * sB + (long long)n0 * K;
    const __nv_bfloat16* Blt = Bl + bz * sB + (long long)n0 * K;

    // warp tiling: 8 warps = 4(m) x 2(n); warp tile 32(m) x 64(n)
    const int wm = (wid & 3) * 32;
    const int wn = (wid >> 2) * 64;
    const int qq = lane >> 3;
    const int rr = lane & 7;

    float acc[2][8][4];
    #pragma unroll
    for (int mi = 0; mi < 2; mi++)
        #pragma unroll
        for (int ni = 0; ni < 8; ni++)
            #pragma unroll
            for (int c = 0; c < 4; c++) acc[mi][ni][c] = 0.0f;

    const int nch = K / 64;

    fill_stage(sbase, Aht, Alt, Bht, Blt, K, tid);
    if (nch > 1)
        fill_stage(sbase + STAGE_BYTES, Aht + 64, Alt + 64, Bht + 64, Blt + 64, K, tid);

    for (int it = 0; it < nch; ++it) {
        if (it + 1 < nch) cp_wait1(); else cp_wait0();
        __syncthreads();

        const uint32_t st = sbase + (uint32_t)(it % NSTAGE) * STAGE_BYTES;

        #pragma unroll
        for (int ks = 0; ks < 4; ++ks) {
            const int ko = ks * 16;
            uint32_t ah[2][4], al[2][4], bb[4][4];
            uint32_t aoff[2], boff[4];
            #pragma unroll
            for (int mi = 0; mi < 2; ++mi) {
                aoff[mi] = sw128((uint32_t)((wm + mi * 16 + rr + (qq & 1) * 8) * 128
                                            + (ko + (qq >> 1) * 8) * 2));
                ldm_x4(ah[mi], st + aoff[mi]);
                ldm_x4(al[mi], st + 16384 + aoff[mi]);
            }
            #pragma unroll
            for (int bi = 0; bi < 4; ++bi) {
                boff[bi] = sw128((uint32_t)((wn + bi * 16 + rr + (qq >> 1) * 8) * 128
                                            + (ko + (qq & 1) * 8) * 2));
                ldm_x4(bb[bi], st + 32768 + boff[bi]);
            }
            // hi*hi
            #pragma unroll
            for (int mi = 0; mi < 2; ++mi)
                #pragma unroll
                for (int ni = 0; ni < 8; ++ni)
                    mma_bf16(acc[mi][ni], ah[mi],
                             bb[ni >> 1][(ni & 1) * 2], bb[ni >> 1][(ni & 1) * 2 + 1]);
            // lo*hi
            #pragma unroll
            for (int mi = 0; mi < 2; ++mi)
                #pragma unroll
                for (int ni = 0; ni < 8; ++ni)
                    mma_bf16(acc[mi][ni], al[mi],
                             bb[ni >> 1][(ni & 1) * 2], bb[ni >> 1][(ni & 1) * 2 + 1]);
            // hi*lo (reload bb with B_lo)
            #pragma unroll
            for (int bi = 0; bi < 4; ++bi)
                ldm_x4(bb[bi], st + 49152 + boff[bi]);
            #pragma unroll
            for (int mi = 0; mi < 2; ++mi)
                #pragma unroll
                for (int ni = 0; ni < 8; ++ni)
                    mma_bf16(acc[mi][ni], ah[mi],
                             bb[ni >> 1][(ni & 1) * 2], bb[ni >> 1][(ni & 1) * 2 + 1]);
        }

        if (it + 2 < nch) {
            const int k0 = (it + 2) * 64;
            fill_stage(sbase + (uint32_t)((it + 2) % NSTAGE) * STAGE_BYTES,
                       Aht + k0, Alt + k0, Bht + k0, Blt + k0, K, tid);
        }
    }

    // epilogue
    const int g  = lane >> 2;
    const int t4 = lane & 3;
    #pragma unroll
    for (int mi = 0; mi < 2; ++mi) {
        const int row = m0 + wm + mi * 16 + g;
        #pragma unroll
        for (int ni = 0; ni < 8; ++ni) {
            const int col = n0 + wn + ni * 8 + t4 * 2;
            float b0 = 0.0f, b1 = 0.0f;
            if (bias) { b0 = bias[col]; b1 = bias[col + 1]; }
            const float v00 = acc[mi][ni][0] + b0, v01 = acc[mi][ni][1] + b1;
            const float v10 = acc[mi][ni][2] + b0, v11 = acc[mi][ni][3] + b1;
            if (Cf) {
                float* cg = Cf + bz * sC;
                *reinterpret_cast<float2*>(&cg[(long long)row * N + col])
                    = make_float2(v00, v01);
                *reinterpret_cast<float2*>(&cg[(long long)(row + 8) * N + col])
                    = make_float2(v10, v11);
            }
            if (Ch) {
                uint32_t h, l;
                split2(v00, v01, h, l);
                *reinterpret_cast<uint32_t*>(&Ch[bz * sC + (long long)row * N + col]) = h;
                *reinterpret_cast<uint32_t*>(&Cl[bz * sC + (long long)row * N + col]) = l;
                split2(v10, v11, h, l);
                *reinterpret_cast<uint32_t*>(&Ch[bz * sC + (long long)(row + 8) * N + col]) = h;
                *reinterpret_cast<uint32_t*>(&Cl[bz * sC + (long long)(row + 8) * N + col]) = l;
            }
        }
    }
}

// ---------------------------------------------------------------------------
// Single-pass row softmax (row length 2048, 256 threads, 8 floats in regs)
// reads fp32 energy, writes hi/lo bf16 attn.
// ---------------------------------------------------------------------------
__global__ __launch_bounds__(256) void softmax_split_kernel(
    const float* __restrict__ en,
    __nv_bfloat16* __restrict__ hi, __nv_bfloat16* __restrict__ lo)
{
    const size_t base = (size_t)blockIdx.x * NN;
    const int tid = threadIdx.x;
    const float4* src = reinterpret_cast<const float4*>(en + base);
    __shared__ float red[8];

    float4 v0 = src[tid];
    float4 v1 = src[tid + 256];

    float m = fmaxf(fmaxf(fmaxf(v0.x, v0.y), fmaxf(v0.z, v0.w)),
                    fmaxf(fmaxf(v1.x, v1.y), fmaxf(v1.z, v1.w)));
    #pragma unroll
    for (int o = 16; o; o >>= 1) m = fmaxf(m, __shfl_xor_sync(0xffffffffu, m, o));
    if ((tid & 31) == 0) red[tid >> 5] = m;
    __syncthreads();
    m = red[0];
    #pragma unroll
    for (int w = 1; w < 8; ++w) m = fmaxf(m, red[w]);

    v0.x = __expf(v0.x - m); v0.y = __expf(v0.y - m);
    v0.z = __expf(v0.z - m); v0.w = __expf(v0.w - m);
    v1.x = __expf(v1.x - m); v1.y = __expf(v1.y - m);
    v1.z = __expf(v1.z - m); v1.w = __expf(v1.w - m);

    float s = v0.x + v0.y + v0.z + v0.w + v1.x + v1.y + v1.z + v1.w;
    #pragma unroll
    for (int o = 16; o; o >>= 1) s += __shfl_xor_sync(0xffffffffu, s, o);
    __syncthreads();
    if ((tid & 31) == 0) red[tid >> 5] = s;
    __syncthreads();
    s = red[0];
    #pragma unroll
    for (int w = 1; w < 8; ++w) s += red[w];
    const float inv = 1.0f / s;

    uint2* ph = reinterpret_cast<uint2*>(hi + base);
    uint2* pl = reinterpret_cast<uint2*>(lo + base);
    uint32_t h0, l0, h1, l1;
    split2(v0.x * inv, v0.y * inv, h0, l0);
    split2(v0.z * inv, v0.w * inv, h1, l1);
    ph[tid] = make_uint2(h0, h1);
    pl[tid] = make_uint2(l0, l1);
    split2(v1.x * inv, v1.y * inv, h0, l0);
    split2(v1.z * inv, v1.w * inv, h1, l1);
    ph[tid + 256] = make_uint2(h0, h1);
    pl[tid + 256] = make_uint2(l0, l1);
}

// ---------------------------------------------------------------------------
// Launch
// ---------------------------------------------------------------------------
extern "C" void kernel_launch(void* const* d_in, const int* in_sizes, int n_in,
                              void* d_out, int out_size)
{
    const float* logits   = (const float*)d_in[0];  // [B,L,N]
    const float* features = (const float*)d_in[1];  // [B,N,C]
    const float* Wq       = (const float*)d_in[2];  // [D,C]
    const float* bq       = (const float*)d_in[3];  // [D]
    const float* Wk       = (const float*)d_in[4];  // [D,C]
    const float* bk       = (const float*)d_in[5];  // [D]
    float* out            = (float*)d_out;          // [B,L,N]

    __nv_bfloat16 *feat_h, *feat_l, *log_h, *log_l;
    __nv_bfloat16 *wq_h, *wq_l, *wk_h, *wk_l;
    __nv_bfloat16 *q_h, *q_l, *k_h, *k_l, *attn_h, *attn_l;
    float* energy;
    cudaGetSymbolAddress((void**)&feat_h, g_feat_h);
    cudaGetSymbolAddress((void**)&feat_l, g_feat_l);
    cudaGetSymbolAddress((void**)&log_h,  g_log_h);
    cudaGetSymbolAddress((void**)&log_l,  g_log_l);
    cudaGetSymbolAddress((void**)&wq_h,   g_wq_h);
    cudaGetSymbolAddress((void**)&wq_l,   g_wq_l);
    cudaGetSymbolAddress((void**)&wk_h,   g_wk_h);
    cudaGetSymbolAddress((void**)&wk_l,   g_wk_l);
    cudaGetSymbolAddress((void**)&q_h,    g_q_h);
    cudaGetSymbolAddress((void**)&q_l,    g_q_l);
    cudaGetSymbolAddress((void**)&k_h,    g_k_h);
    cudaGetSymbolAddress((void**)&k_l,    g_k_l);
    cudaGetSymbolAddress((void**)&attn_h, g_attn_h);
    cudaGetSymbolAddress((void**)&attn_l, g_attn_l);
    cudaGetSymbolAddress((void**)&energy, g_energy);

    cudaFuncSetAttribute(hgemm_nt,
                         cudaFuncAttributeMaxDynamicSharedMemorySize, GSMEM);

    // 0) splits
    {
        int n4 = BB * NN * CC / 4;
        split_kernel<<<n4 / 256, 256>>>((const float4*)features,
                                        (uint2*)feat_h, (uint2*)feat_l, n4);
        n4 = BB * LL * NN / 4;
        split_kernel<<<n4 / 256, 256>>>((const float4*)logits,
                                        (uint2*)log_h, (uint2*)log_l, n4);
        n4 = DD * CC / 4;
        split_kernel<<<n4 / 256, 256>>>((const float4*)Wq,
                                        (uint2*)wq_h, (uint2*)wq_l, n4);
        split_kernel<<<n4 / 256, 256>>>((const float4*)Wk,
                                        (uint2*)wk_h, (uint2*)wk_l, n4);
    }

    // 1+2) Projections: [B*N,C] x [D,C]^T -> bf16 hi/lo q,k
    hgemm_nt<<<dim3(1, (BB * NN) / 128, 1), 256, GSMEM>>>(
        feat_h, feat_l, wq_h, wq_l, nullptr, q_h, q_l, bq,
        BB * NN, DD, CC, 0, 0, 0);
    hgemm_nt<<<dim3(1, (BB * NN) / 128, 1), 256, GSMEM>>>(
        feat_h, feat_l, wk_h, wk_l, nullptr, k_h, k_l, bk,
        BB * NN, DD, CC, 0, 0, 0);

    // 3) Energy: per batch Q[2048,128] @ K^T -> fp32
    hgemm_nt<<<dim3(NN / 128, NN / 128, BB), 256, GSMEM>>>(
        q_h, q_l, k_h, k_l, energy, nullptr, nullptr, nullptr,
        NN, NN, DD,
        (long long)NN * DD, (long long)NN * DD, (long long)NN * NN);

    // 4) Softmax (single pass) -> attn hi/lo bf16
    softmax_split_kernel<<<BB * NN, 256>>>(energy, attn_h, attn_l);

    // 5) Aggregation: out[b,l,m] = sum_n logits[b,l,n]*attn[b,m,n]
    hgemm_nt<<<dim3(NN / 128, LL / 128, BB), 256, GSMEM>>>(
        log_h, log_l, attn_h, attn_l, out, nullptr, nullptr, nullptr,
        LL, NN, NN,
        (long long)LL * NN, (long long)NN * NN, (long long)LL * NN);
}